// round 3
// baseline (speedup 1.0000x reference)
#include <cuda_runtime.h>
#include <cstdint>
#include <cstdio>

// ---------------- problem constants ----------------
#define TPB    256
#define GROUP  28          // batch elements per block
#define NBLK   147         // 147 * 28 = 4116 >= 4096 = B
#define BTOT   4096

#define T_IN   96
#define T_OUTC 32
#define TT     128         // decoder length
#define INF    8
#define H1     64
#define K1     72          // 8 (x) + 64 (h) fused K
#define W1S    76          // padded row stride (floats) for W1 in smem
#define H1STR  68          // padded h row stride
#define HD_STR 20          // decoder row stride

// ---------------- smem layout (float offsets) ----------------
#define OFF_W1   0         // 256*76     = 19456
#define OFF_H    19456     // 2*28*68    = 3808
#define OFF_X    23264     // 28*8       = 224
#define OFF_W2   23488     // 4*68       = 272
#define OFF_W2HB 23760     // 8
#define OFF_G2   23768     // 112
#define OFF_H2   23880     // 28
#define OFF_U    23908     // 28
#define OFF_WD1  23936     // 64*20      = 1280
#define OFF_HD   25216     // 2*28*20    = 1120
#define OFF_WD2  26336     // 80
#define OFF_G2D  26416     // 112
#define OFF_H2D  26528     // 28
#define OFF_DOUT 26556     // 28*128     = 3584
#define OFF_TMP  30140     // 28*32      = 896
#define SMEM_FLOATS 31036  // 124144 bytes

__device__ __forceinline__ float sigf(float v) {
    return __fdividef(1.0f, 1.0f + __expf(-v));
}
__device__ __forceinline__ float tanhf_fast(float v) {
    return 2.0f * __fdividef(1.0f, 1.0f + __expf(-2.0f * v)) - 1.0f;
}

__global__ void __launch_bounds__(TPB, 1)
lstm_net_kernel(const float* __restrict__ x,
                const float* __restrict__ e1Wih, const float* __restrict__ e1Whh, const float* __restrict__ e1b,
                const float* __restrict__ e2Wih, const float* __restrict__ e2Whh, const float* __restrict__ e2b,
                const float* __restrict__ d1Wih, const float* __restrict__ d1Whh, const float* __restrict__ d1b,
                const float* __restrict__ d2Wih, const float* __restrict__ d2Whh, const float* __restrict__ d2b,
                const float* __restrict__ fc1W, const float* __restrict__ fc1b,
                const float* __restrict__ fc2W, const float* __restrict__ fc2b,
                float* __restrict__ out)
{
    extern __shared__ float sm[];
    const int tid  = threadIdx.x;
    const int e0g  = blockIdx.x * GROUP;

    // ---------------- stage weights into smem ----------------
    for (int idx = tid; idx < 256 * K1; idx += TPB) {
        int r = idx / K1;
        int k = idx - r * K1;
        sm[OFF_W1 + r * W1S + k] = (k < INF) ? e1Wih[r * INF + k]
                                             : e1Whh[r * H1 + (k - INF)];
    }
    for (int idx = tid; idx < 4 * H1; idx += TPB) {
        int g = idx >> 6, k = idx & 63;
        sm[OFF_W2 + g * H1STR + k] = e2Wih[g * H1 + k];
    }
    if (tid < 4) { sm[OFF_W2HB + tid] = e2Whh[tid]; sm[OFF_W2HB + 4 + tid] = e2b[tid]; }
    for (int idx = tid; idx < 64 * 16; idx += TPB) {
        int j = idx >> 4, k = idx & 15;
        sm[OFF_WD1 + j * HD_STR + k] = d1Whh[j * 16 + k];
    }
    if (tid < 64) {
        sm[OFF_WD1 + tid * HD_STR + 16] = d1Wih[tid];
        sm[OFF_WD1 + tid * HD_STR + 17] = d1b[tid];
        int g = tid >> 4, k = tid & 15;
        sm[OFF_WD2 + g * HD_STR + k] = d2Wih[g * 16 + k];
    }
    if (tid < 4) {
        sm[OFF_WD2 + tid * HD_STR + 16] = d2Whh[tid];
        sm[OFF_WD2 + tid * HD_STR + 17] = d2b[tid];
    }
    for (int idx = tid; idx < 2 * GROUP * H1STR; idx += TPB) sm[OFF_H + idx]  = 0.f;
    for (int idx = tid; idx < 2 * GROUP * HD_STR; idx += TPB) sm[OFF_HD + idx] = 0.f;
    if (tid < GROUP) { sm[OFF_H2 + tid] = 0.f; sm[OFF_H2D + tid] = 0.f; }
    __syncthreads();

    // ---------------- per-thread tiling ----------------
    // e1: thread owns unit u (0..63) x 4 gates x 7 elems {E0+4j}
    const int U  = tid >> 2;        // 0..63
    const int E0 = tid & 3;
    int   RB[4];                    // float4 row bases into W1
    float b1r[4];
    #pragma unroll
    for (int g = 0; g < 4; ++g) {
        int row = (g << 6) + U;
        RB[g]  = row * (W1S / 4);
        b1r[g] = e1b[row];
    }
    float c1[7];
    #pragma unroll
    for (int j = 0; j < 7; ++j) c1[j] = 0.f;

    float c2  = 0.f;     // e2 cell state (threads 0..27)
    float c2d = 0.f;     // d2 cell state (threads 0..27)

    // decoder d1: thread owns unit UD (0..15) x 4 gates x elems {EB, EB+16}
    const int UD = tid & 15;
    const int EB = tid >> 4;        // 0..15
    const bool eb2ok = (EB + 16) < GROUP;   // second elem valid?
    float cd0 = 0.f, cd1 = 0.f;
    float d1wi[4], d1wb[4];
    #pragma unroll
    for (int g = 0; g < 4; ++g) {
        int row = (g << 4) + UD;
        d1wi[g] = sm[OFF_WD1 + row * HD_STR + 16];
        d1wb[g] = sm[OFF_WD1 + row * HD_STR + 17];
    }

    int p = 0, pd = 0;

    // ---------------- unified time loop ----------------
    for (int t = 0; t < TT; ++t) {
        if (t < T_IN) {
            // stage x[:, t, :] for this block (clamped for ragged tail)
            if (tid < GROUP * INF) {
                int e = tid >> 3, i = tid & 7;
                int eg = e0g + e; if (eg >= BTOT) eg = BTOT - 1;
                sm[OFF_X + e * 8 + i] = x[(size_t)eg * (T_IN * INF) + t * INF + i];
            }
            __syncthreads();

            // ---- e1 gates: [28 x 256] = [x_t | h] @ W1^T ----
            const float4* __restrict__ W14 = (const float4*)(sm + OFF_W1);
            const float4* __restrict__ x4  = (const float4*)(sm + OFF_X);
            const float4* __restrict__ h4  = (const float4*)(sm + OFF_H) + p * (GROUP * H1STR / 4);

            float acc[4][7];
            #pragma unroll
            for (int g = 0; g < 4; ++g)
                #pragma unroll
                for (int j = 0; j < 7; ++j) acc[g][j] = b1r[g];

            #pragma unroll
            for (int kk = 0; kk < 2; ++kk) {           // x part (K = 0..7)
                float4 a[7];
                #pragma unroll
                for (int j = 0; j < 7; ++j) a[j] = x4[(E0 + 4 * j) * 2 + kk];
                #pragma unroll
                for (int g = 0; g < 4; ++g) {
                    float4 wv = W14[RB[g] + kk];
                    #pragma unroll
                    for (int j = 0; j < 7; ++j) {
                        acc[g][j] += a[j].x * wv.x;
                        acc[g][j] += a[j].y * wv.y;
                        acc[g][j] += a[j].z * wv.z;
                        acc[g][j] += a[j].w * wv.w;
                    }
                }
            }
            #pragma unroll 4
            for (int kk = 0; kk < 16; ++kk) {          // h part (K = 8..71)
                float4 a[7];
                #pragma unroll
                for (int j = 0; j < 7; ++j) a[j] = h4[(E0 + 4 * j) * 17 + kk];
                #pragma unroll
                for (int g = 0; g < 4; ++g) {
                    float4 wv = W14[RB[g] + 2 + kk];
                    #pragma unroll
                    for (int j = 0; j < 7; ++j) {
                        acc[g][j] += a[j].x * wv.x;
                        acc[g][j] += a[j].y * wv.y;
                        acc[g][j] += a[j].z * wv.z;
                        acc[g][j] += a[j].w * wv.w;
                    }
                }
            }

            // ---- e1 nonlinearity + h write ----
            float* hn = sm + OFF_H + (1 - p) * (GROUP * H1STR);
            #pragma unroll
            for (int j = 0; j < 7; ++j) {
                float ig = sigf(acc[0][j]);
                float fg = sigf(acc[1][j]);
                float gg = tanhf_fast(acc[2][j]);
                float og = sigf(acc[3][j]);
                float c  = fg * c1[j] + ig * gg;
                c1[j] = c;
                hn[(E0 + 4 * j) * H1STR + U] = og * tanhf_fast(c);
            }
            __syncthreads();

            // ---- e2 gates (hidden=1): threads 0..111 ----
            if (tid < 4 * GROUP) {
                int e = tid >> 2, g = tid & 3;
                float s = sm[OFF_W2HB + 4 + g] + sm[OFF_W2HB + g] * sm[OFF_H2 + e];
                const float4* hr = (const float4*)(sm + OFF_H + (1 - p) * (GROUP * H1STR) + e * H1STR);
                const float4* w2 = (const float4*)(sm + OFF_W2 + g * H1STR);
                #pragma unroll
                for (int k = 0; k < 16; ++k) {
                    float4 a = hr[k], b = w2[k];
                    s += a.x * b.x + a.y * b.y + a.z * b.z + a.w * b.w;
                }
                sm[OFF_G2 + tid] = s;
            }
            __syncthreads();

            // ---- e2 state + relu -> decoder input u ----
            if (tid < GROUP) {
                float ig = sigf(sm[OFF_G2 + tid * 4 + 0]);
                float fg = sigf(sm[OFF_G2 + tid * 4 + 1]);
                float gg = tanhf_fast(sm[OFF_G2 + tid * 4 + 2]);
                float og = sigf(sm[OFF_G2 + tid * 4 + 3]);
                c2 = fg * c2 + ig * gg;
                float h2 = og * tanhf_fast(c2);
                sm[OFF_H2 + tid] = h2;
                sm[OFF_U + tid]  = fmaxf(h2, 0.f);
            }
            p ^= 1;
        } else {
            // decoder tail: u = x[:, T_IN-T_OUT + (t-T_IN), 0]
            if (tid < GROUP) {
                int eg = e0g + tid; if (eg >= BTOT) eg = BTOT - 1;
                sm[OFF_U + tid] =
                    x[(size_t)eg * (T_IN * INF) + (T_IN - T_OUTC + (t - T_IN)) * INF];
            }
        }
        __syncthreads();  // u ready (and hd1 prev-step writes visible)

        // ---- d1 (in=1, hidden=16) ----
        {
            float accd0[4], accd1[4];
            float u0 = sm[OFF_U + EB];
            float u1 = sm[OFF_U + (eb2ok ? (EB + 16) : EB)];
            #pragma unroll
            for (int g = 0; g < 4; ++g) {
                accd0[g] = d1wb[g] + d1wi[g] * u0;
                accd1[g] = d1wb[g] + d1wi[g] * u1;
            }
            const float4* hd4 = (const float4*)(sm + OFF_HD) + pd * (GROUP * HD_STR / 4);
            const int e1i = eb2ok ? (EB + 16) : EB;
            #pragma unroll
            for (int k = 0; k < 4; ++k) {
                float4 a0 = hd4[EB * 5 + k];
                float4 a1 = hd4[e1i * 5 + k];
                #pragma unroll
                for (int g = 0; g < 4; ++g) {
                    const float4 wv = *(const float4*)(sm + OFF_WD1 + ((g << 4) + UD) * HD_STR + 4 * k);
                    accd0[g] += a0.x * wv.x + a0.y * wv.y + a0.z * wv.z + a0.w * wv.w;
                    accd1[g] += a1.x * wv.x + a1.y * wv.y + a1.z * wv.z + a1.w * wv.w;
                }
            }
            float* hdn = sm + OFF_HD + (1 - pd) * (GROUP * HD_STR);
            {
                float ig = sigf(accd0[0]), fg = sigf(accd0[1]);
                float gg = tanhf_fast(accd0[2]), og = sigf(accd0[3]);
                cd0 = fg * cd0 + ig * gg;
                hdn[EB * HD_STR + UD] = og * tanhf_fast(cd0);
            }
            if (eb2ok) {
                float ig = sigf(accd1[0]), fg = sigf(accd1[1]);
                float gg = tanhf_fast(accd1[2]), og = sigf(accd1[3]);
                cd1 = fg * cd1 + ig * gg;
                hdn[(EB + 16) * HD_STR + UD] = og * tanhf_fast(cd1);
            }
        }
        __syncthreads();

        // ---- d2 gates (in=16, hidden=1): threads 0..111 ----
        if (tid < 4 * GROUP) {
            int e = tid >> 2, g = tid & 3;
            float s = sm[OFF_WD2 + g * HD_STR + 17]
                    + sm[OFF_WD2 + g * HD_STR + 16] * sm[OFF_H2D + e];
            const float4* hr = (const float4*)(sm + OFF_HD + (1 - pd) * (GROUP * HD_STR) + e * HD_STR);
            #pragma unroll
            for (int k = 0; k < 4; ++k) {
                float4 a = hr[k];
                const float4 b = *(const float4*)(sm + OFF_WD2 + g * HD_STR + 4 * k);
                s += a.x * b.x + a.y * b.y + a.z * b.z + a.w * b.w;
            }
            sm[OFF_G2D + tid] = s;
        }
        __syncthreads();

        // ---- d2 state -> dout[t] ----
        if (tid < GROUP) {
            float ig = sigf(sm[OFF_G2D + tid * 4 + 0]);
            float fg = sigf(sm[OFF_G2D + tid * 4 + 1]);
            float gg = tanhf_fast(sm[OFF_G2D + tid * 4 + 2]);
            float og = sigf(sm[OFF_G2D + tid * 4 + 3]);
            c2d = fg * c2d + ig * gg;
            float hh = og * tanhf_fast(c2d);
            sm[OFF_H2D + tid]           = hh;
            sm[OFF_DOUT + tid * TT + t] = hh;
        }
        pd ^= 1;
    }
    __syncthreads();

    // ---------------- FC head ----------------
    #pragma unroll
    for (int r = 0; r < 4; ++r) {
        int idx = tid + TPB * r;
        if (idx < GROUP * 32) {
            int e = idx >> 5, j = idx & 31;
            float s = fc1b[j];
            const float4* dr = (const float4*)(sm + OFF_DOUT + e * TT);
            const float4* wr = (const float4*)(fc1W + j * TT);
            #pragma unroll 8
            for (int k = 0; k < 32; ++k) {
                float4 a = dr[k], b = wr[k];
                s += a.x * b.x + a.y * b.y + a.z * b.z + a.w * b.w;
            }
            sm[OFF_TMP + e * 32 + j] = s;
        }
    }
    __syncthreads();
    #pragma unroll
    for (int r = 0; r < 4; ++r) {
        int idx = tid + TPB * r;
        if (idx < GROUP * 32) {
            int e = idx >> 5, o = idx & 31;
            if (e0g + e < BTOT) {
                float s = fc2b[o];
                const float4* tr = (const float4*)(sm + OFF_TMP + e * 32);
                const float4* wr = (const float4*)(fc2W + o * 32);
                #pragma unroll
                for (int k = 0; k < 8; ++k) {
                    float4 a = tr[k], b = wr[k];
                    s += a.x * b.x + a.y * b.y + a.z * b.z + a.w * b.w;
                }
                out[(size_t)(e0g + e) * T_OUTC + o] = s;
            }
        }
    }
}

extern "C" void kernel_launch(void* const* d_in, const int* in_sizes, int n_in,
                              void* d_out, int out_size) {
    (void)in_sizes; (void)n_in; (void)out_size;
    const float* x      = (const float*)d_in[0];
    const float* e1Wih  = (const float*)d_in[1];
    const float* e1Whh  = (const float*)d_in[2];
    const float* e1b    = (const float*)d_in[3];
    const float* e2Wih  = (const float*)d_in[4];
    const float* e2Whh  = (const float*)d_in[5];
    const float* e2b    = (const float*)d_in[6];
    const float* d1Wih  = (const float*)d_in[7];
    const float* d1Whh  = (const float*)d_in[8];
    const float* d1b    = (const float*)d_in[9];
    const float* d2Wih  = (const float*)d_in[10];
    const float* d2Whh  = (const float*)d_in[11];
    const float* d2b    = (const float*)d_in[12];
    const float* fc1W   = (const float*)d_in[13];
    const float* fc1b   = (const float*)d_in[14];
    const float* fc2W   = (const float*)d_in[15];
    const float* fc2b   = (const float*)d_in[16];

    const size_t smem = SMEM_FLOATS * sizeof(float);  // 124144 B
    cudaFuncSetAttribute(lstm_net_kernel,
                         cudaFuncAttributeMaxDynamicSharedMemorySize, (int)smem);
    lstm_net_kernel<<<NBLK, TPB, smem>>>(x,
        e1Wih, e1Whh, e1b, e2Wih, e2Whh, e2b,
        d1Wih, d1Whh, d1b, d2Wih, d2Whh, d2b,
        fc1W, fc1b, fc2W, fc2b, (float*)d_out);
}

// round 4
// speedup vs baseline: 1.1138x; 1.1138x over previous
#include <cuda_runtime.h>
#include <cstdint>
#include <cstdio>

// ---------------- problem constants ----------------
#define TPB    384         // 256 e1 workers + 128 decoder workers
#define E1T    256
#define GROUP  28          // batch elements per block
#define NBLK   147         // 147 * 28 = 4116 >= 4096
#define BTOT   4096

#define T_IN   96
#define T_OUTC 32
#define TT     128
#define INF    8
#define H1     64
#define K1     72
#define W1S    76          // padded W1 row stride (floats)
#define H1STR  68          // padded h row stride
#define HD_STR 20          // decoder row stride
#define XSTR   224         // x_s per-t stride = 28*8

// ---------------- smem layout (float offsets) ----------------
#define OFF_W1   0         // 19456
#define OFF_H    19456     // 2*28*68 = 3808
#define OFF_W2   23264     // 272
#define OFF_W2HB 23536     // 8
#define OFF_G2   23544     // 112
#define OFF_H2   23656     // 28
#define OFF_U    23684     // 28
#define OFF_WD1  23712     // 1280
#define OFF_HD   24992     // 1120
#define OFF_WD2  26112     // 80
#define OFF_G2D  26192     // 112
#define OFF_H2D  26304     // 28
#define OFF_DOUT 26332     // 28*128 = 3584
#define OFF_TMP  29916     // 896
#define OFF_XS   30812     // 96*224 = 21504
#define SMEM_FLOATS 52316  // 209264 bytes

// named barriers
#define BARSYNC(id,cnt) asm volatile("bar.sync %0, %1;"   :: "r"(id), "r"(cnt) : "memory")
#define BARARR(id,cnt)  asm volatile("bar.arrive %0, %1;" :: "r"(id), "r"(cnt) : "memory")

__device__ __forceinline__ float sigf(float v) {
    return __fdividef(1.0f, 1.0f + __expf(-v));
}
__device__ __forceinline__ float tanhf_fast(float v) {
    return 2.0f * __fdividef(1.0f, 1.0f + __expf(-2.0f * v)) - 1.0f;
}

__global__ void __launch_bounds__(TPB, 1)
lstm_net_kernel(const float* __restrict__ x,
                const float* __restrict__ e1Wih, const float* __restrict__ e1Whh, const float* __restrict__ e1b,
                const float* __restrict__ e2Wih, const float* __restrict__ e2Whh, const float* __restrict__ e2b,
                const float* __restrict__ d1Wih, const float* __restrict__ d1Whh, const float* __restrict__ d1b,
                const float* __restrict__ d2Wih, const float* __restrict__ d2Whh, const float* __restrict__ d2b,
                const float* __restrict__ fc1W, const float* __restrict__ fc1b,
                const float* __restrict__ fc2W, const float* __restrict__ fc2b,
                float* __restrict__ out)
{
    extern __shared__ float sm[];
    const int tid  = threadIdx.x;
    const int e0g  = blockIdx.x * GROUP;

    // ---------------- stage weights + x slice into smem ----------------
    for (int idx = tid; idx < 256 * K1; idx += TPB) {
        int r = idx / K1;
        int k = idx - r * K1;
        sm[OFF_W1 + r * W1S + k] = (k < INF) ? e1Wih[r * INF + k]
                                             : e1Whh[r * H1 + (k - INF)];
    }
    for (int idx = tid; idx < 4 * H1; idx += TPB) {
        int g = idx >> 6, k = idx & 63;
        sm[OFF_W2 + g * H1STR + k] = e2Wih[g * H1 + k];
    }
    if (tid < 4) { sm[OFF_W2HB + tid] = e2Whh[tid]; sm[OFF_W2HB + 4 + tid] = e2b[tid]; }
    for (int idx = tid; idx < 64 * 16; idx += TPB) {
        int j = idx >> 4, k = idx & 15;
        sm[OFF_WD1 + j * HD_STR + k] = d1Whh[j * 16 + k];
    }
    if (tid < 64) {
        sm[OFF_WD1 + tid * HD_STR + 16] = d1Wih[tid];
        sm[OFF_WD1 + tid * HD_STR + 17] = d1b[tid];
        int g = tid >> 4, k = tid & 15;
        sm[OFF_WD2 + g * HD_STR + k] = d2Wih[g * 16 + k];
    }
    if (tid < 4) {
        sm[OFF_WD2 + tid * HD_STR + 16] = d2Whh[tid];
        sm[OFF_WD2 + tid * HD_STR + 17] = d2b[tid];
    }
    // full x slice for this block: [t][e][i], stride XSTR per t
    for (int idx = tid; idx < GROUP * T_IN * INF; idx += TPB) {
        int e = idx / (T_IN * INF);
        int r = idx - e * (T_IN * INF);
        int eg = e0g + e; if (eg >= BTOT) eg = BTOT - 1;
        sm[OFF_XS + (r >> 3) * XSTR + e * 8 + (r & 7)] = x[(size_t)eg * (T_IN * INF) + r];
    }
    for (int idx = tid; idx < 2 * GROUP * H1STR; idx += TPB) sm[OFF_H + idx]  = 0.f;
    for (int idx = tid; idx < 2 * GROUP * HD_STR; idx += TPB) sm[OFF_HD + idx] = 0.f;
    if (tid < GROUP) { sm[OFF_H2 + tid] = 0.f; sm[OFF_H2D + tid] = 0.f; }
    __syncthreads();

    if (tid < E1T) {
        // =========================================================
        //                    e1 worker group
        // thread owns unit U (0..63) x 4 gates x 7 elems {E0+4j}
        // =========================================================
        const int U  = tid >> 2;
        const int E0 = tid & 3;
        int   RB[4];
        float b1r[4];
        #pragma unroll
        for (int g = 0; g < 4; ++g) {
            int row = (g << 6) + U;
            RB[g]  = row * (W1S / 4);
            b1r[g] = e1b[row];
        }
        float c1[7];
        #pragma unroll
        for (int j = 0; j < 7; ++j) c1[j] = 0.f;

        int p = 0;
        for (int t = 0; t < T_IN; ++t) {
            if (t >= 2)      BARSYNC(3 + (t & 1), TPB);   // buffer (1-p) free (decoder t-2 done)
            else if (t == 1) BARSYNC(6, E1T);             // e1-internal: h(t=0) visible

            const float4* __restrict__ W14 = (const float4*)(sm + OFF_W1);
            const float4* __restrict__ x4  = (const float4*)(sm + OFF_XS + t * XSTR);
            const float4* __restrict__ h4  = (const float4*)(sm + OFF_H) + p * (GROUP * H1STR / 4);

            float acc[4][7];
            #pragma unroll
            for (int g = 0; g < 4; ++g)
                #pragma unroll
                for (int j = 0; j < 7; ++j) acc[g][j] = b1r[g];

            #pragma unroll
            for (int kk = 0; kk < 2; ++kk) {            // x part (K=0..7)
                float4 a[7];
                #pragma unroll
                for (int j = 0; j < 7; ++j) a[j] = x4[(E0 + 4 * j) * 2 + kk];
                #pragma unroll
                for (int g = 0; g < 4; ++g) {
                    float4 wv = W14[RB[g] + kk];
                    #pragma unroll
                    for (int j = 0; j < 7; ++j) {
                        acc[g][j] += a[j].x * wv.x;
                        acc[g][j] += a[j].y * wv.y;
                        acc[g][j] += a[j].z * wv.z;
                        acc[g][j] += a[j].w * wv.w;
                    }
                }
            }
            #pragma unroll 4
            for (int kk = 0; kk < 16; ++kk) {           // h part (K=8..71)
                float4 a[7];
                #pragma unroll
                for (int j = 0; j < 7; ++j) a[j] = h4[(E0 + 4 * j) * 17 + kk];
                #pragma unroll
                for (int g = 0; g < 4; ++g) {
                    float4 wv = W14[RB[g] + 2 + kk];
                    #pragma unroll
                    for (int j = 0; j < 7; ++j) {
                        acc[g][j] += a[j].x * wv.x;
                        acc[g][j] += a[j].y * wv.y;
                        acc[g][j] += a[j].z * wv.z;
                        acc[g][j] += a[j].w * wv.w;
                    }
                }
            }

            float* hn = sm + OFF_H + (1 - p) * (GROUP * H1STR);
            #pragma unroll
            for (int j = 0; j < 7; ++j) {
                float ig = sigf(acc[0][j]);
                float fg = sigf(acc[1][j]);
                float gg = tanhf_fast(acc[2][j]);
                float og = sigf(acc[3][j]);
                float c  = fg * c1[j] + ig * gg;
                c1[j] = c;
                hn[(E0 + 4 * j) * H1STR + U] = og * tanhf_fast(c);
            }
            BARARR(1 + (t & 1), TPB);                   // h(t) ready
            p ^= 1;
        }
    } else {
        // =========================================================
        //                 decoder worker group (128 thr)
        // =========================================================
        const int dt = tid - E1T;              // 0..127
        const int UD = dt & 15;
        const int EB = dt >> 4;                // 0..7
        float cd[4] = {0.f, 0.f, 0.f, 0.f};
        float c2  = 0.f;                       // e2 state (dt<28)
        float c2d = 0.f;                       // d2 state (dt<28)
        float d1wi[4], d1wb[4];
        #pragma unroll
        for (int g = 0; g < 4; ++g) {
            int row = (g << 4) + UD;
            d1wi[g] = sm[OFF_WD1 + row * HD_STR + 16];
            d1wb[g] = sm[OFF_WD1 + row * HD_STR + 17];
        }

        int pd = 0;
        for (int t = 0; t < TT; ++t) {
            if (t < T_IN) {
                BARSYNC(1 + (t & 1), TPB);             // wait h(t)
                const int hb = 1 - (t & 1);            // buffer e1 wrote at step t
                float s = 0.f;
                if (dt < 4 * GROUP) {
                    int e = dt >> 2, g = dt & 3;
                    s = sm[OFF_W2HB + 4 + g] + sm[OFF_W2HB + g] * sm[OFF_H2 + e];
                    const float4* hr = (const float4*)(sm + OFF_H + hb * (GROUP * H1STR) + e * H1STR);
                    const float4* w2 = (const float4*)(sm + OFF_W2 + g * H1STR);
                    #pragma unroll
                    for (int k = 0; k < 16; ++k) {
                        float4 a = hr[k], b = w2[k];
                        s += a.x * b.x + a.y * b.y + a.z * b.z + a.w * b.w;
                    }
                }
                BARARR(3 + (t & 1), TPB);              // done reading h buffer
                if (dt < 4 * GROUP) sm[OFF_G2 + dt] = s;
                BARSYNC(5, TPB - E1T);
                if (dt < GROUP) {
                    float ig = sigf(sm[OFF_G2 + dt * 4 + 0]);
                    float fg = sigf(sm[OFF_G2 + dt * 4 + 1]);
                    float gg = tanhf_fast(sm[OFF_G2 + dt * 4 + 2]);
                    float og = sigf(sm[OFF_G2 + dt * 4 + 3]);
                    c2 = fg * c2 + ig * gg;
                    float h2 = og * tanhf_fast(c2);
                    sm[OFF_H2 + dt] = h2;
                    sm[OFF_U + dt]  = fmaxf(h2, 0.f);
                }
            } else {
                // u = x[:, 64 + (t-96), 0]  -> x_s[(t-32)*XSTR + e*8]
                if (dt < GROUP)
                    sm[OFF_U + dt] = sm[OFF_XS + (t - 32) * XSTR + dt * 8];
            }
            BARSYNC(5, TPB - E1T);                     // u ready

            // ---- d1 (in=1, hidden=16): unit UD x elems {EB+8m} ----
            {
                const float4* hd4 = (const float4*)(sm + OFF_HD) + pd * (GROUP * HD_STR / 4);
                float* hdn = sm + OFF_HD + (1 - pd) * (GROUP * HD_STR);
                #pragma unroll
                for (int m = 0; m < 4; ++m) {
                    int e = EB + 8 * m;
                    if (e < GROUP) {
                        float um = sm[OFF_U + e];
                        float a0 = d1wb[0] + d1wi[0] * um;
                        float a1 = d1wb[1] + d1wi[1] * um;
                        float a2 = d1wb[2] + d1wi[2] * um;
                        float a3 = d1wb[3] + d1wi[3] * um;
                        #pragma unroll
                        for (int k = 0; k < 4; ++k) {
                            float4 av = hd4[e * 5 + k];
                            #pragma unroll
                            for (int g = 0; g < 4; ++g) {
                                const float4 wv = *(const float4*)(sm + OFF_WD1 + ((g << 4) + UD) * HD_STR + 4 * k);
                                float d = av.x * wv.x + av.y * wv.y + av.z * wv.z + av.w * wv.w;
                                if (g == 0) a0 += d; else if (g == 1) a1 += d;
                                else if (g == 2) a2 += d; else a3 += d;
                            }
                        }
                        float ig = sigf(a0), fg = sigf(a1);
                        float gg = tanhf_fast(a2), og = sigf(a3);
                        float c = fg * cd[m] + ig * gg;
                        cd[m] = c;
                        hdn[e * HD_STR + UD] = og * tanhf_fast(c);
                    }
                }
            }
            BARSYNC(5, TPB - E1T);

            // ---- d2 gates (in=16, hidden=1) ----
            if (dt < 4 * GROUP) {
                int e = dt >> 2, g = dt & 3;
                float s = sm[OFF_WD2 + g * HD_STR + 17]
                        + sm[OFF_WD2 + g * HD_STR + 16] * sm[OFF_H2D + e];
                const float4* hr = (const float4*)(sm + OFF_HD + (1 - pd) * (GROUP * HD_STR) + e * HD_STR);
                #pragma unroll
                for (int k = 0; k < 4; ++k) {
                    float4 a = hr[k];
                    const float4 b = *(const float4*)(sm + OFF_WD2 + g * HD_STR + 4 * k);
                    s += a.x * b.x + a.y * b.y + a.z * b.z + a.w * b.w;
                }
                sm[OFF_G2D + dt] = s;
            }
            BARSYNC(5, TPB - E1T);

            // ---- d2 state -> dout[t] ----
            if (dt < GROUP) {
                float ig = sigf(sm[OFF_G2D + dt * 4 + 0]);
                float fg = sigf(sm[OFF_G2D + dt * 4 + 1]);
                float gg = tanhf_fast(sm[OFF_G2D + dt * 4 + 2]);
                float og = sigf(sm[OFF_G2D + dt * 4 + 3]);
                c2d = fg * c2d + ig * gg;
                float hh = og * tanhf_fast(c2d);
                sm[OFF_H2D + dt]           = hh;
                sm[OFF_DOUT + dt * TT + t] = hh;
            }
            pd ^= 1;
        }
    }
    __syncthreads();

    // ---------------- FC head (all 384 threads) ----------------
    #pragma unroll
    for (int r = 0; r < 3; ++r) {
        int idx = tid + TPB * r;
        if (idx < GROUP * 32) {
            int e = idx >> 5, j = idx & 31;
            float s = fc1b[j];
            const float4* dr = (const float4*)(sm + OFF_DOUT + e * TT);
            const float4* wr = (const float4*)(fc1W + j * TT);
            #pragma unroll 8
            for (int k = 0; k < 32; ++k) {
                float4 a = dr[k], b = wr[k];
                s += a.x * b.x + a.y * b.y + a.z * b.z + a.w * b.w;
            }
            sm[OFF_TMP + e * 32 + j] = s;
        }
    }
    __syncthreads();
    #pragma unroll
    for (int r = 0; r < 3; ++r) {
        int idx = tid + TPB * r;
        if (idx < GROUP * 32) {
            int e = idx >> 5, o = idx & 31;
            if (e0g + e < BTOT) {
                float s = fc2b[o];
                const float4* tr = (const float4*)(sm + OFF_TMP + e * 32);
                const float4* wr = (const float4*)(fc2W + o * 32);
                #pragma unroll
                for (int k = 0; k < 8; ++k) {
                    float4 a = tr[k], b = wr[k];
                    s += a.x * b.x + a.y * b.y + a.z * b.z + a.w * b.w;
                }
                out[(size_t)(e0g + e) * T_OUTC + o] = s;
            }
        }
    }
}

extern "C" void kernel_launch(void* const* d_in, const int* in_sizes, int n_in,
                              void* d_out, int out_size) {
    (void)in_sizes; (void)n_in; (void)out_size;
    const float* x      = (const float*)d_in[0];
    const float* e1Wih  = (const float*)d_in[1];
    const float* e1Whh  = (const float*)d_in[2];
    const float* e1b    = (const float*)d_in[3];
    const float* e2Wih  = (const float*)d_in[4];
    const float* e2Whh  = (const float*)d_in[5];
    const float* e2b    = (const float*)d_in[6];
    const float* d1Wih  = (const float*)d_in[7];
    const float* d1Whh  = (const float*)d_in[8];
    const float* d1b    = (const float*)d_in[9];
    const float* d2Wih  = (const float*)d_in[10];
    const float* d2Whh  = (const float*)d_in[11];
    const float* d2b    = (const float*)d_in[12];
    const float* fc1W   = (const float*)d_in[13];
    const float* fc1b   = (const float*)d_in[14];
    const float* fc2W   = (const float*)d_in[15];
    const float* fc2b   = (const float*)d_in[16];

    const size_t smem = SMEM_FLOATS * sizeof(float);  // 209264 B
    cudaFuncSetAttribute(lstm_net_kernel,
                         cudaFuncAttributeMaxDynamicSharedMemorySize, (int)smem);
    lstm_net_kernel<<<NBLK, TPB, smem>>>(x,
        e1Wih, e1Whh, e1b, e2Wih, e2Whh, e2b,
        d1Wih, d1Whh, d1b, d2Wih, d2Whh, d2b,
        fc1W, fc1b, fc2W, fc2b, (float*)d_out);
}

// round 5
// speedup vs baseline: 1.3220x; 1.1869x over previous
#include <cuda_runtime.h>
#include <cstdint>

// ---------------- problem constants ----------------
#define TPB    384         // 256 e1 (mma) workers + 128 decoder workers
#define E1T    256
#define GROUP  28
#define NBLK   147
#define BTOT   4096

#define T_IN   96
#define T_OUTC 32
#define TT     128
#define INF    8
#define H1     64
#define ASTR   84          // A operand buffer row stride (conflict-free)
#define ABUF   (32*ASTR)   // 2688 floats per A buffer
#define H1STR  68          // e2 weight row stride
#define HD_STR 20

// ---------------- smem layout (float offsets) ----------------
#define OFF_BH   0         // 8*9*4*64 = 18432 (tf32 hi B frags)
#define OFF_BL   18432     // 18432           (tf32 lo B frags)
#define OFF_A    36864     // 2*2688 = 5376   (double-buffered [x|h] operand)
#define OFF_W2   42240     // 272
#define OFF_W2HB 42512     // 8
#define OFF_G2   42520     // 112
#define OFF_H2   42632     // 28
#define OFF_U    42660     // 28
#define OFF_WD1  42688     // 1280
#define OFF_HD   43968     // 1120
#define OFF_WD2  45088     // 80
#define OFF_G2D  45168     // 112
#define OFF_H2D  45280     // 28
#define OFF_DOUT 45308     // 3584
#define OFF_TMP  48892     // 896
#define SMEM_FLOATS 49788  // 199152 bytes

#define BARSYNC(id,cnt) asm volatile("bar.sync %0, %1;"   :: "r"(id), "r"(cnt) : "memory")
#define BARARR(id,cnt)  asm volatile("bar.arrive %0, %1;" :: "r"(id), "r"(cnt) : "memory")

__device__ __forceinline__ float sigf(float v) {
    return __fdividef(1.0f, 1.0f + __expf(-v));
}
__device__ __forceinline__ float tanhf_fast(float v) {
    return 2.0f * __fdividef(1.0f, 1.0f + __expf(-2.0f * v)) - 1.0f;
}
__device__ __forceinline__ unsigned cvt_tf32(float f) {
    unsigned r; asm("cvt.rna.tf32.f32 %0, %1;" : "=r"(r) : "f"(f)); return r;
}
__device__ __forceinline__ void mma_tf32(float* c, const unsigned* a, unsigned b0, unsigned b1) {
    asm volatile(
        "mma.sync.aligned.m16n8k8.row.col.f32.tf32.tf32.f32 "
        "{%0,%1,%2,%3}, {%4,%5,%6,%7}, {%8,%9}, {%0,%1,%2,%3};"
        : "+f"(c[0]), "+f"(c[1]), "+f"(c[2]), "+f"(c[3])
        : "r"(a[0]), "r"(a[1]), "r"(a[2]), "r"(a[3]), "r"(b0), "r"(b1));
}

__global__ void __launch_bounds__(TPB, 1)
lstm_net_kernel(const float* __restrict__ x,
                const float* __restrict__ e1Wih, const float* __restrict__ e1Whh, const float* __restrict__ e1b,
                const float* __restrict__ e2Wih, const float* __restrict__ e2Whh, const float* __restrict__ e2b,
                const float* __restrict__ d1Wih, const float* __restrict__ d1Whh, const float* __restrict__ d1b,
                const float* __restrict__ d2Wih, const float* __restrict__ d2Whh, const float* __restrict__ d2b,
                const float* __restrict__ fc1W, const float* __restrict__ fc1b,
                const float* __restrict__ fc2W, const float* __restrict__ fc2b,
                float* __restrict__ out)
{
    extern __shared__ float sm[];
    const int tid  = threadIdx.x;
    const int e0g  = blockIdx.x * GROUP;

    // ================= init =================
    // B fragments (tf32 hi/lo), gate-interleaved columns: n' = unit*4 + gate
    if (tid < E1T) {
        const int w = tid >> 5, lane = tid & 31;
        unsigned* BHp = (unsigned*)(sm + OFF_BH);
        unsigned* BLp = (unsigned*)(sm + OFF_BL);
        #pragma unroll
        for (int kt = 0; kt < 9; ++kt)
            #pragma unroll
            for (int nt = 0; nt < 4; ++nt)
                #pragma unroll
                for (int rix = 0; rix < 2; ++rix) {
                    int np = w * 32 + nt * 8 + (lane >> 2);       // B column n'
                    int k  = kt * 8 + (lane & 3) + 4 * rix;       // B row (K)
                    int r  = (np & 3) * 64 + (np >> 2);           // W1 row = gate*64+unit
                    float v = (k < INF) ? e1Wih[r * INF + k]
                                        : e1Whh[r * H1 + (k - INF)];
                    unsigned hi = cvt_tf32(v);
                    unsigned lo = cvt_tf32(v - __uint_as_float(hi));
                    int base = ((w * 9 + kt) * 4 + nt) * 64 + rix * 32 + lane;
                    BHp[base] = hi;
                    BLp[base] = lo;
                }
    }
    // zero A buffers (padding rows + h0 = 0)
    for (int idx = tid; idx < 2 * ABUF; idx += TPB) sm[OFF_A + idx] = 0.f;
    // small weights
    for (int idx = tid; idx < 4 * H1; idx += TPB) {
        int g = idx >> 6, k = idx & 63;
        sm[OFF_W2 + g * H1STR + k] = e2Wih[g * H1 + k];
    }
    if (tid < 4) { sm[OFF_W2HB + tid] = e2Whh[tid]; sm[OFF_W2HB + 4 + tid] = e2b[tid]; }
    for (int idx = tid; idx < 64 * 16; idx += TPB) {
        int j = idx >> 4, k = idx & 15;
        sm[OFF_WD1 + j * HD_STR + k] = d1Whh[j * 16 + k];
    }
    if (tid < 64) {
        sm[OFF_WD1 + tid * HD_STR + 16] = d1Wih[tid];
        sm[OFF_WD1 + tid * HD_STR + 17] = d1b[tid];
        int g = tid >> 4, k = tid & 15;
        sm[OFF_WD2 + g * HD_STR + k] = d2Wih[g * 16 + k];
    }
    if (tid < 4) {
        sm[OFF_WD2 + tid * HD_STR + 16] = d2Whh[tid];
        sm[OFF_WD2 + tid * HD_STR + 17] = d2b[tid];
    }
    for (int idx = tid; idx < 2 * GROUP * HD_STR; idx += TPB) sm[OFF_HD + idx] = 0.f;
    if (tid < GROUP) { sm[OFF_H2 + tid] = 0.f; sm[OFF_H2D + tid] = 0.f; }
    __syncthreads();
    // x_0 into A[0] cols 0..7
    if (tid < GROUP * INF) {
        int e = tid >> 3, i = tid & 7;
        int eg = e0g + e; if (eg >= BTOT) eg = BTOT - 1;
        sm[OFF_A + e * ASTR + i] = x[(size_t)eg * (T_IN * INF) + i];
    }
    __syncthreads();

    if (tid < E1T) {
        // =========================================================
        //         e1 worker group: TF32x3 tensor-core LSTM
        // warp w owns B columns [32w, 32w+32) (= units 8w..8w+7, all gates)
        // =========================================================
        const int w = tid >> 5, lane = tid & 31;
        const int gid = lane >> 2, tq = lane & 3;
        const bool qe = ((tq & 1) == 0);

        float bI[4], bF[4], bG[4], bO[4];
        int un[4];
        #pragma unroll
        for (int nt = 0; nt < 4; ++nt) {
            int u = 8 * w + 2 * nt + (tq >> 1);
            un[nt] = u;
            bI[nt] = e1b[u];
            bF[nt] = e1b[64 + u];
            bG[nt] = e1b[128 + u];
            bO[nt] = e1b[192 + u];
        }
        float cs[8];
        #pragma unroll
        for (int i = 0; i < 8; ++i) cs[i] = 0.f;

        const int xe = tid >> 3, xi = tid & 7;   // x loader role (tid<224)
        int xeg = e0g + xe; if (xeg >= BTOT) xeg = BTOT - 1;

        const unsigned* __restrict__ BHp = (const unsigned*)(sm + OFF_BH);
        const unsigned* __restrict__ BLp = (const unsigned*)(sm + OFF_BL);

        for (int t = 0; t < T_IN; ++t) {
            if (t >= 2)      BARSYNC(3 + (t & 1), TPB);   // A-next free (decoder done)
            else if (t == 1) BARSYNC(6, E1T);             // h0/x1 visible within e1

            const float* __restrict__ Ac = sm + OFF_A + (t & 1) * ABUF;
            float* __restrict__       An = sm + OFF_A + ((t + 1) & 1) * ABUF;

            // prefetch next x (hidden under MMA work)
            float xv = 0.f;
            if ((t + 1 < T_IN) && tid < GROUP * INF)
                xv = x[(size_t)xeg * (T_IN * INF) + (t + 1) * INF + xi];

            float acc[2][4][4];
            #pragma unroll
            for (int mt = 0; mt < 2; ++mt)
                #pragma unroll
                for (int nt = 0; nt < 4; ++nt)
                    #pragma unroll
                    for (int i = 0; i < 4; ++i) acc[mt][nt][i] = 0.f;

            #pragma unroll
            for (int kt = 0; kt < 9; ++kt) {
                unsigned ah[2][4], al[2][4];
                #pragma unroll
                for (int mt = 0; mt < 2; ++mt) {
                    const float* ap = Ac + (mt * 16 + gid) * ASTR + kt * 8 + tq;
                    float a0 = ap[0];
                    float a1 = ap[8 * ASTR];
                    float a2 = ap[4];
                    float a3 = ap[8 * ASTR + 4];
                    ah[mt][0] = cvt_tf32(a0); al[mt][0] = cvt_tf32(a0 - __uint_as_float(ah[mt][0]));
                    ah[mt][1] = cvt_tf32(a1); al[mt][1] = cvt_tf32(a1 - __uint_as_float(ah[mt][1]));
                    ah[mt][2] = cvt_tf32(a2); al[mt][2] = cvt_tf32(a2 - __uint_as_float(ah[mt][2]));
                    ah[mt][3] = cvt_tf32(a3); al[mt][3] = cvt_tf32(a3 - __uint_as_float(ah[mt][3]));
                }
                #pragma unroll
                for (int nt = 0; nt < 4; ++nt) {
                    int bb = ((w * 9 + kt) * 4 + nt) * 64 + lane;
                    unsigned bh0 = BHp[bb], bh1 = BHp[bb + 32];
                    unsigned bl0 = BLp[bb], bl1 = BLp[bb + 32];
                    mma_tf32(acc[0][nt], ah[0], bh0, bh1);
                    mma_tf32(acc[0][nt], al[0], bh0, bh1);
                    mma_tf32(acc[0][nt], ah[0], bl0, bl1);
                    mma_tf32(acc[1][nt], ah[1], bh0, bh1);
                    mma_tf32(acc[1][nt], al[1], bh0, bh1);
                    mma_tf32(acc[1][nt], ah[1], bl0, bl1);
                }
            }

            // ---- LSTM cell epilogue: lane-pair gate exchange ----
            #pragma unroll
            for (int mt = 0; mt < 2; ++mt)
                #pragma unroll
                for (int nt = 0; nt < 4; ++nt) {
                    float c0 = acc[mt][nt][0], c1 = acc[mt][nt][1];
                    float c2 = acc[mt][nt][2], c3 = acc[mt][nt][3];
                    float v0 = qe ? c2 : c0, v1 = qe ? c3 : c1;
                    float r0 = __shfl_xor_sync(0xffffffffu, v0, 1);
                    float r1 = __shfl_xor_sync(0xffffffffu, v1, 1);
                    float gi = qe ? c0 : r0;
                    float gf = qe ? c1 : r1;
                    float gg = qe ? r0 : c2;
                    float go = qe ? r1 : c3;
                    int row = mt * 16 + gid + (qe ? 0 : 8);
                    float cc  = cs[mt * 4 + nt];
                    float igv = sigf(gi + bI[nt]);
                    float fgv = sigf(gf + bF[nt]);
                    float ggv = tanhf_fast(gg + bG[nt]);
                    float ogv = sigf(go + bO[nt]);
                    cc = fgv * cc + igv * ggv;
                    cs[mt * 4 + nt] = cc;
                    An[row * ASTR + 8 + un[nt]] = ogv * tanhf_fast(cc);
                }
            if ((t + 1 < T_IN) && tid < GROUP * INF)
                An[xe * ASTR + xi] = xv;

            BARARR(1 + (t & 1), TPB);                     // h(t) ready
        }
    } else {
        // =========================================================
        //                 decoder worker group (128 thr)
        // =========================================================
        const int dt = tid - E1T;
        const int UD = dt & 15;
        const int EB = dt >> 4;
        float cd[4] = {0.f, 0.f, 0.f, 0.f};
        float c2  = 0.f;
        float c2d = 0.f;
        float d1wi[4], d1wb[4];
        #pragma unroll
        for (int g = 0; g < 4; ++g) {
            int row = (g << 4) + UD;
            d1wi[g] = sm[OFF_WD1 + row * HD_STR + 16];
            d1wb[g] = sm[OFF_WD1 + row * HD_STR + 17];
        }

        int pd = 0;
        for (int t = 0; t < TT; ++t) {
            if (t < T_IN) {
                BARSYNC(1 + (t & 1), TPB);                // wait h(t)
                const float* hb = sm + OFF_A + ((t + 1) & 1) * ABUF;  // h_t at cols 8..71
                float s = 0.f;
                if (dt < 4 * GROUP) {
                    int e = dt >> 2, g = dt & 3;
                    s = sm[OFF_W2HB + 4 + g] + sm[OFF_W2HB + g] * sm[OFF_H2 + e];
                    const float4* hr = (const float4*)(hb + e * ASTR + 8);
                    const float4* w2 = (const float4*)(sm + OFF_W2 + g * H1STR);
                    #pragma unroll
                    for (int k = 0; k < 16; ++k) {
                        float4 a = hr[k], b = w2[k];
                        s += a.x * b.x + a.y * b.y + a.z * b.z + a.w * b.w;
                    }
                }
                BARARR(3 + (t & 1), TPB);                 // done reading h buffer
                if (dt < 4 * GROUP) sm[OFF_G2 + dt] = s;
                BARSYNC(5, TPB - E1T);
                if (dt < GROUP) {
                    float ig = sigf(sm[OFF_G2 + dt * 4 + 0]);
                    float fg = sigf(sm[OFF_G2 + dt * 4 + 1]);
                    float gg = tanhf_fast(sm[OFF_G2 + dt * 4 + 2]);
                    float og = sigf(sm[OFF_G2 + dt * 4 + 3]);
                    c2 = fg * c2 + ig * gg;
                    float h2 = og * tanhf_fast(c2);
                    sm[OFF_H2 + dt] = h2;
                    sm[OFF_U + dt]  = fmaxf(h2, 0.f);
                }
            } else {
                if (dt < GROUP) {
                    int eg = e0g + dt; if (eg >= BTOT) eg = BTOT - 1;
                    sm[OFF_U + dt] = x[(size_t)eg * (T_IN * INF) + (t - 32) * INF];
                }
            }
            BARSYNC(5, TPB - E1T);                        // u ready

            // ---- d1 (in=1, hidden=16) ----
            {
                const float4* hd4 = (const float4*)(sm + OFF_HD) + pd * (GROUP * HD_STR / 4);
                float* hdn = sm + OFF_HD + (1 - pd) * (GROUP * HD_STR);
                #pragma unroll
                for (int m = 0; m < 4; ++m) {
                    int e = EB + 8 * m;
                    if (e < GROUP) {
                        float um = sm[OFF_U + e];
                        float a0 = d1wb[0] + d1wi[0] * um;
                        float a1 = d1wb[1] + d1wi[1] * um;
                        float a2 = d1wb[2] + d1wi[2] * um;
                        float a3 = d1wb[3] + d1wi[3] * um;
                        #pragma unroll
                        for (int k = 0; k < 4; ++k) {
                            float4 av = hd4[e * 5 + k];
                            #pragma unroll
                            for (int g = 0; g < 4; ++g) {
                                const float4 wv = *(const float4*)(sm + OFF_WD1 + ((g << 4) + UD) * HD_STR + 4 * k);
                                float d = av.x * wv.x + av.y * wv.y + av.z * wv.z + av.w * wv.w;
                                if (g == 0) a0 += d; else if (g == 1) a1 += d;
                                else if (g == 2) a2 += d; else a3 += d;
                            }
                        }
                        float ig = sigf(a0), fg = sigf(a1);
                        float gg = tanhf_fast(a2), og = sigf(a3);
                        float c = fg * cd[m] + ig * gg;
                        cd[m] = c;
                        hdn[e * HD_STR + UD] = og * tanhf_fast(c);
                    }
                }
            }
            BARSYNC(5, TPB - E1T);

            // ---- d2 gates ----
            if (dt < 4 * GROUP) {
                int e = dt >> 2, g = dt & 3;
                float s = sm[OFF_WD2 + g * HD_STR + 17]
                        + sm[OFF_WD2 + g * HD_STR + 16] * sm[OFF_H2D + e];
                const float4* hr = (const float4*)(sm + OFF_HD + (1 - pd) * (GROUP * HD_STR) + e * HD_STR);
                #pragma unroll
                for (int k = 0; k < 4; ++k) {
                    float4 a = hr[k];
                    const float4 b = *(const float4*)(sm + OFF_WD2 + g * HD_STR + 4 * k);
                    s += a.x * b.x + a.y * b.y + a.z * b.z + a.w * b.w;
                }
                sm[OFF_G2D + dt] = s;
            }
            BARSYNC(5, TPB - E1T);

            // ---- d2 state -> dout[t] ----
            if (dt < GROUP) {
                float ig = sigf(sm[OFF_G2D + dt * 4 + 0]);
                float fg = sigf(sm[OFF_G2D + dt * 4 + 1]);
                float gg = tanhf_fast(sm[OFF_G2D + dt * 4 + 2]);
                float og = sigf(sm[OFF_G2D + dt * 4 + 3]);
                c2d = fg * c2d + ig * gg;
                float hh = og * tanhf_fast(c2d);
                sm[OFF_H2D + dt]           = hh;
                sm[OFF_DOUT + dt * TT + t] = hh;
            }
            pd ^= 1;
        }
    }
    __syncthreads();

    // ---------------- FC head (all 384 threads) ----------------
    #pragma unroll
    for (int r = 0; r < 3; ++r) {
        int idx = tid + TPB * r;
        if (idx < GROUP * 32) {
            int e = idx >> 5, j = idx & 31;
            float s = fc1b[j];
            const float4* dr = (const float4*)(sm + OFF_DOUT + e * TT);
            const float4* wr = (const float4*)(fc1W + j * TT);
            #pragma unroll 8
            for (int k = 0; k < 32; ++k) {
                float4 a = dr[k], b = wr[k];
                s += a.x * b.x + a.y * b.y + a.z * b.z + a.w * b.w;
            }
            sm[OFF_TMP + e * 32 + j] = s;
        }
    }
    __syncthreads();
    #pragma unroll
    for (int r = 0; r < 3; ++r) {
        int idx = tid + TPB * r;
        if (idx < GROUP * 32) {
            int e = idx >> 5, o = idx & 31;
            if (e0g + e < BTOT) {
                float s = fc2b[o];
                const float4* tr = (const float4*)(sm + OFF_TMP + e * 32);
                const float4* wr = (const float4*)(fc2W + o * 32);
                #pragma unroll
                for (int k = 0; k < 8; ++k) {
                    float4 a = tr[k], b = wr[k];
                    s += a.x * b.x + a.y * b.y + a.z * b.z + a.w * b.w;
                }
                out[(size_t)(e0g + e) * T_OUTC + o] = s;
            }
        }
    }
}

extern "C" void kernel_launch(void* const* d_in, const int* in_sizes, int n_in,
                              void* d_out, int out_size) {
    (void)in_sizes; (void)n_in; (void)out_size;
    const float* x      = (const float*)d_in[0];
    const float* e1Wih  = (const float*)d_in[1];
    const float* e1Whh  = (const float*)d_in[2];
    const float* e1b    = (const float*)d_in[3];
    const float* e2Wih  = (const float*)d_in[4];
    const float* e2Whh  = (const float*)d_in[5];
    const float* e2b    = (const float*)d_in[6];
    const float* d1Wih  = (const float*)d_in[7];
    const float* d1Whh  = (const float*)d_in[8];
    const float* d1b    = (const float*)d_in[9];
    const float* d2Wih  = (const float*)d_in[10];
    const float* d2Whh  = (const float*)d_in[11];
    const float* d2b    = (const float*)d_in[12];
    const float* fc1W   = (const float*)d_in[13];
    const float* fc1b   = (const float*)d_in[14];
    const float* fc2W   = (const float*)d_in[15];
    const float* fc2b   = (const float*)d_in[16];

    const size_t smem = SMEM_FLOATS * sizeof(float);  // 199152 B
    cudaFuncSetAttribute(lstm_net_kernel,
                         cudaFuncAttributeMaxDynamicSharedMemorySize, (int)smem);
    lstm_net_kernel<<<NBLK, TPB, smem>>>(x,
        e1Wih, e1Whh, e1b, e2Wih, e2Whh, e2b,
        d1Wih, d1Whh, d1b, d2Wih, d2Whh, d2b,
        fc1W, fc1b, fc2W, fc2b, (float*)d_out);
}